// round 14
// baseline (speedup 1.0000x reference)
#include <cuda_runtime.h>

#define NODE_F 8
#define EDGE_F 2
#define HID 16
#define NMAX 100000
#define EMAX 1600000
#define ESTEPS 8    // edges per block = 32 * ESTEPS = 256
#define SCAN_T 1024

// ---- constant-memory weights (filled by async D2D memcpy each call) ----
__constant__ float c_eW1[3 * 19 * HID];  // 912
__constant__ float c_eW2[3 * HID * 2];   // 96
__constant__ float c_eb2[3 * 2];         // 6
__constant__ float c_nW1[3 * 11 * HID];  // 528
__constant__ float c_nW2[3 * HID * 8];   // 384
__constant__ float c_nb2[3 * 8];         // 24

// ---- scratch (__device__ globals per allocation-free rule) ----
__device__ alignas(16) float d_xA[NMAX * NODE_F];
__device__ alignas(16) float d_xB[NMAX * NODE_F];
__device__ alignas(16) float2 d_ea[EMAX];         // edge embeddings (sorted order)
__device__ alignas(16) float2 d_eaP[EMAX];        // permuted input edge_attr
__device__ alignas(16) int2  d_sortedRC[EMAX];    // (r, c) sorted by r
__device__ alignas(16) float d_p[NMAX * HID];     // A_l . x[n]  (64B row)
__device__ alignas(16) float d_q[NMAX * HID];     // B_l . x[n]
__device__ alignas(16) float d_agg[NMAX * EDGE_F];   // zero-init, self-cleaning
__device__ int  d_cnt[NMAX];     // zero-init; re-zeroed by node_kernel<2>
__device__ int  d_start[NMAX];   // rebuilt by scan each call
__device__ float d_g;
__device__ float d_eacc[EDGE_F];   // zero-init, self-cleaning
__device__ float d_nacc[NODE_F];   // zero-init, self-cleaning
__device__ float d_ebias[2][HID];
__device__ float d_nbias[2][HID];
__device__ unsigned d_count;       // zero-init, self-cleaning

// ---------------------------------------------------------------------------
// layer-0 p/q precompute from external x; block 0 also folds layer-0 biases.
__global__ __launch_bounds__(256)
void pre_kernel(const float* __restrict__ x,
                const float* __restrict__ g_in,
                const float* __restrict__ eb1, const float* __restrict__ nb1,
                float* __restrict__ ebias0, float* __restrict__ nbias0, int N)
{
    if (blockIdx.x == 0 && threadIdx.x < 32) {
        int t = threadIdx.x;
        float g = g_in[0];
        if (t < HID) {
            ebias0[t] = eb1[t] + g * c_eW1[t];
            nbias0[t] = nb1[t] + g * c_nW1[t];
        }
        if (t == 0) d_g = g;
    }
    int n = blockIdx.x * blockDim.x + threadIdx.x;
    if (n >= N) return;
    float xv[NODE_F];
    *reinterpret_cast<float4*>(xv)     = *reinterpret_cast<const float4*>(x + (size_t)n * NODE_F);
    *reinterpret_cast<float4*>(xv + 4) = *reinterpret_cast<const float4*>(x + (size_t)n * NODE_F + 4);
    float pv[HID], qv[HID];
    #pragma unroll
    for (int j = 0; j < HID; j++) { pv[j] = 0.f; qv[j] = 0.f; }
    #pragma unroll
    for (int k = 0; k < NODE_F; k++) {
        float v = xv[k];
        #pragma unroll
        for (int j = 0; j < HID; j++) {
            pv[j] = fmaf(v, c_eW1[(1 + k) * HID + j], pv[j]);
            qv[j] = fmaf(v, c_eW1[(9 + k) * HID + j], qv[j]);
        }
    }
    float4* pd = reinterpret_cast<float4*>(d_p + (size_t)n * HID);
    float4* qd = reinterpret_cast<float4*>(d_q + (size_t)n * HID);
    #pragma unroll
    for (int v = 0; v < 4; v++) {
        pd[v] = reinterpret_cast<float4*>(pv)[v];
        qd[v] = reinterpret_cast<float4*>(qv)[v];
    }
}

// ---------------------------------------------------------------------------
// Counting sort by r. Pass 1: histogram.
__global__ __launch_bounds__(256)
void hist_kernel(const int* __restrict__ ei, int E)
{
    int e = blockIdx.x * blockDim.x + threadIdx.x;
    if (e < E) atomicAdd(&d_cnt[__ldcs(ei + e)], 1);
}

// Pass 2: exclusive prefix sum (single block, chunked Hillis-Steele).
__global__ __launch_bounds__(SCAN_T)
void scan_kernel(int N)
{
    __shared__ int part[SCAN_T];
    const int t = threadIdx.x;
    const int chunk = (N + SCAN_T - 1) / SCAN_T;
    const int base = t * chunk;
    int s = 0;
    for (int i = 0; i < chunk; i++) {
        int idx = base + i;
        if (idx < N) s += d_cnt[idx];
    }
    part[t] = s;
    __syncthreads();
    for (int off = 1; off < SCAN_T; off <<= 1) {
        int add = (t >= off) ? part[t - off] : 0;
        __syncthreads();
        part[t] += add;
        __syncthreads();
    }
    int run = part[t] - s;   // exclusive prefix of this chunk
    for (int i = 0; i < chunk; i++) {
        int idx = base + i;
        if (idx < N) { d_start[idx] = run; run += d_cnt[idx]; }
    }
}

// Pass 3: permute edges into sorted-by-r order (mutates d_start as cursors).
__global__ __launch_bounds__(256)
void perm_kernel(const int* __restrict__ ei, const float* __restrict__ ea0, int E)
{
    int e = blockIdx.x * blockDim.x + threadIdx.x;
    if (e >= E) return;
    int r = __ldcs(ei + e);
    int c = __ldcs(ei + E + e);
    int pos = atomicAdd(&d_start[r], 1);
    d_sortedRC[pos] = make_int2(r, c);
    d_eaP[pos] = __ldcs(reinterpret_cast<const float2*>(ea0 + (size_t)e * EDGE_F));
}

// ---------------------------------------------------------------------------
// Edge block on SORTED edges: consecutive edges share r -> p-gather and the
// agg scatter touch ~1.5 lines per warp-instruction instead of 8.
template<int L, bool WRITE_EA>
__global__ __launch_bounds__(128, 12)
void edge_kernel(const float2* __restrict__ eaIn,
                 const float* __restrict__ ebias,
                 float2* __restrict__ ea_out, int E)
{
    __shared__ int    sR[32 * ESTEPS], sC[32 * ESTEPS];
    __shared__ float2 sEA[32 * ESTEPS];
    const int tx    = threadIdx.x;
    const int sub   = tx & 3;
    const int group = tx >> 2;        // 0..31
    const int j0    = sub * 4;
    const int base  = blockIdx.x * (32 * ESTEPS);

    #pragma unroll
    for (int i = tx; i < 32 * ESTEPS; i += 128) {
        int e  = base + i;
        int ec = (e < E) ? e : 0;
        int2 v = __ldcs(d_sortedRC + ec);
        sR[i]  = v.x;
        sC[i]  = v.y;
        sEA[i] = __ldcs(eaIn + ec);
    }

    float c0[4], c1[4], w20[4], w21[4], ebv[4];
    #pragma unroll
    for (int k = 0; k < 4; k++) {
        c0[k]  = c_eW1[L * 304 + 17 * HID + j0 + k];
        c1[k]  = c_eW1[L * 304 + 18 * HID + j0 + k];
        w20[k] = c_eW2[L * 32 + 2 * (j0 + k)];
        w21[k] = c_eW2[L * 32 + 2 * (j0 + k) + 1];
        ebv[k] = ebias[j0 + k];
    }
    const float B20 = c_eb2[L * 2 + 0];
    const float B21 = c_eb2[L * 2 + 1];
    __syncthreads();

    #pragma unroll
    for (int s = 0; s < ESTEPS; s++) {
        const int le = group + s * 32;
        const int e  = base + le;
        if (e < E) {
            int r = sR[le];
            int c = sC[le];
            float4 pv = *reinterpret_cast<const float4*>(d_p + (size_t)r * HID + j0);
            float4 qv = *reinterpret_cast<const float4*>(d_q + (size_t)c * HID + j0);
            float2 eav = sEA[le];

            float o0 = 0.f, o1 = 0.f;
            float hp[4] = {pv.x, pv.y, pv.z, pv.w};
            float hq[4] = {qv.x, qv.y, qv.z, qv.w};
            #pragma unroll
            for (int k = 0; k < 4; k++) {
                float h = ebv[k] + hp[k] + hq[k];
                h = fmaf(eav.x, c0[k], h);
                h = fmaf(eav.y, c1[k], h);
                h = fmaxf(h, 0.f);
                o0 = fmaf(h, w20[k], o0);
                o1 = fmaf(h, w21[k], o1);
            }
            o0 += __shfl_xor_sync(0xffffffffu, o0, 1);
            o1 += __shfl_xor_sync(0xffffffffu, o1, 1);
            o0 += __shfl_xor_sync(0xffffffffu, o0, 2);
            o1 += __shfl_xor_sync(0xffffffffu, o1, 2);

            if (sub == 0) {
                o0 += B20; o1 += B21;
                if (WRITE_EA)
                    ea_out[e] = make_float2(o0, o1);
                float* dst = &d_agg[(size_t)r * EDGE_F];
                asm volatile("red.global.add.v2.f32 [%0], {%1, %2};"
                             :: "l"(dst), "f"(o0), "f"(o1) : "memory");
            }
        }
    }
}

// ---------------------------------------------------------------------------
// Node block: weights from __constant__ with compile-time layer L.
// FUSE: next-layer p/q, node+edge sums, last block runs the global MLP.
// Non-FUSE (last layer): also re-zeroes d_cnt for the next call's histogram.
template<int L, bool FUSE>
__global__ __launch_bounds__(256)
void node_kernel(const float* __restrict__ x,
                 const float* __restrict__ nbias,
                 float* __restrict__ x_out,
                 const float* __restrict__ gW1, const float* __restrict__ gb1,
                 const float* __restrict__ gW2, const float* __restrict__ gb2,
                 const float* __restrict__ eb1n, const float* __restrict__ nb1n,
                 float* __restrict__ ebias_out, float* __restrict__ nbias_out,
                 float invE, float invN, int N)
{
    __shared__ float sNb[HID];
    __shared__ float sred[NODE_F + 2][8];
    __shared__ bool  isLast;
    int tx = threadIdx.x;
    if (tx < HID) sNb[tx] = nbias[tx];
    __syncthreads();

    int n = blockIdx.x * blockDim.x + tx;
    float out[NODE_F];
    #pragma unroll
    for (int k = 0; k < NODE_F; k++) out[k] = 0.f;
    float2 av = make_float2(0.f, 0.f);

    if (n < N) {
        if (!FUSE) d_cnt[n] = 0;   // self-clean histogram for next call
        float xv[NODE_F];
        *reinterpret_cast<float4*>(xv)     = *reinterpret_cast<const float4*>(x + (size_t)n * NODE_F);
        *reinterpret_cast<float4*>(xv + 4) = *reinterpret_cast<const float4*>(x + (size_t)n * NODE_F + 4);
        av = *reinterpret_cast<float2*>(&d_agg[(size_t)n * EDGE_F]);
        *reinterpret_cast<float2*>(&d_agg[(size_t)n * EDGE_F]) = make_float2(0.f, 0.f);

        float h[HID];
        #pragma unroll
        for (int j = 0; j < HID; j++) h[j] = sNb[j];
        #pragma unroll
        for (int i = 0; i < NODE_F; i++) {
            float v = xv[i];
            #pragma unroll
            for (int j = 0; j < HID; j++)
                h[j] = fmaf(v, c_nW1[L * 176 + (1 + i) * HID + j], h[j]);
        }
        #pragma unroll
        for (int j = 0; j < HID; j++) {
            h[j] = fmaf(av.x, c_nW1[L * 176 + 9 * HID + j], h[j]);
            h[j] = fmaf(av.y, c_nW1[L * 176 + 10 * HID + j], h[j]);
        }
        #pragma unroll
        for (int k = 0; k < NODE_F; k++) out[k] = c_nb2[L * 8 + k];
        #pragma unroll
        for (int j = 0; j < HID; j++) {
            float hv = fmaxf(h[j], 0.f);
            #pragma unroll
            for (int k = 0; k < NODE_F; k++)
                out[k] = fmaf(hv, c_nW2[L * 128 + j * 8 + k], out[k]);
        }
        *reinterpret_cast<float4*>(x_out + (size_t)n * NODE_F)     = *reinterpret_cast<float4*>(out);
        *reinterpret_cast<float4*>(x_out + (size_t)n * NODE_F + 4) = *reinterpret_cast<float4*>(out + 4);

        if (FUSE) {
            constexpr int EOFF = (L + 1) * 304;
            float pv[HID], qv[HID];
            #pragma unroll
            for (int j = 0; j < HID; j++) { pv[j] = 0.f; qv[j] = 0.f; }
            #pragma unroll
            for (int k = 0; k < NODE_F; k++) {
                float v = out[k];
                #pragma unroll
                for (int j = 0; j < HID; j++) {
                    pv[j] = fmaf(v, c_eW1[EOFF + (1 + k) * HID + j], pv[j]);
                    qv[j] = fmaf(v, c_eW1[EOFF + (9 + k) * HID + j], qv[j]);
                }
            }
            float4* pd = reinterpret_cast<float4*>(d_p + (size_t)n * HID);
            float4* qd = reinterpret_cast<float4*>(d_q + (size_t)n * HID);
            #pragma unroll
            for (int v = 0; v < 4; v++) {
                pd[v] = reinterpret_cast<float4*>(pv)[v];
                qd[v] = reinterpret_cast<float4*>(qv)[v];
            }
        }
    }

    if (FUSE) {
        int warp = tx >> 5, lane = tx & 31;
        #pragma unroll
        for (int k = 0; k < NODE_F + 2; k++) {
            float s = (k < NODE_F) ? out[k] : ((k == NODE_F) ? av.x : av.y);
            #pragma unroll
            for (int off = 16; off; off >>= 1)
                s += __shfl_down_sync(0xffffffffu, s, off);
            if (lane == 0) sred[k][warp] = s;
        }
        __syncthreads();
        if (tx < NODE_F + 2) {
            float t = 0.f;
            #pragma unroll
            for (int w = 0; w < 8; w++) t += sred[tx][w];
            if (tx < NODE_F) atomicAdd(&d_nacc[tx], t);
            else             atomicAdd(&d_eacc[tx - NODE_F], t);
            __threadfence();
        }
        __syncthreads();
        if (tx == 0) {
            unsigned t = atomicAdd(&d_count, 1u);
            isLast = (t == gridDim.x - 1);
        }
        __syncthreads();

        if (isLast) {
            __threadfence();
            if (tx < 32) {
                float gv = d_g;
                float h = 0.f;
                if (tx < HID) {
                    h = gb1[tx];
                    #pragma unroll
                    for (int i = 0; i < NODE_F; i++)
                        h = fmaf(d_nacc[i] * invN, gW1[i * HID + tx], h);
                    h = fmaf(d_eacc[0] * invE, gW1[8 * HID + tx], h);
                    h = fmaf(d_eacc[1] * invE, gW1[9 * HID + tx], h);
                    h = fmaf(gv, gW1[10 * HID + tx], h);
                    h = fmaxf(h, 0.f) * gW2[tx];
                }
                #pragma unroll
                for (int off = 16; off; off >>= 1)
                    h += __shfl_down_sync(0xffffffffu, h, off);
                float gn = __shfl_sync(0xffffffffu, h, 0) + gb2[0];
                if (tx == 0) d_g = gn;
                if (tx < HID) {
                    ebias_out[tx] = eb1n[tx] + gn * c_eW1[(L + 1) * 304 + tx];
                    nbias_out[tx] = nb1n[tx] + gn * c_nW1[(L + 1) * 176 + tx];
                }
                if (tx < NODE_F) d_nacc[tx] = 0.f;
                if (tx < EDGE_F) d_eacc[tx] = 0.f;
                if (tx == 0)     d_count = 0u;
            }
        }
    }
}

// ---------------------------------------------------------------------------
extern "C" void kernel_launch(void* const* d_in, const int* in_sizes, int n_in,
                              void* d_out, int out_size)
{
    const float* x0  = (const float*)d_in[0];
    const int*   ei  = (const int*)  d_in[1];
    const float* ea0 = (const float*)d_in[2];
    const float* g0  = (const float*)d_in[3];
    const float* eW1 = (const float*)d_in[4];
    const float* eb1 = (const float*)d_in[5];
    const float* eW2 = (const float*)d_in[6];
    const float* eb2 = (const float*)d_in[7];
    const float* nW1 = (const float*)d_in[8];
    const float* nb1 = (const float*)d_in[9];
    const float* nW2 = (const float*)d_in[10];
    const float* nb2 = (const float*)d_in[11];
    const float* gW1 = (const float*)d_in[12];
    const float* gb1 = (const float*)d_in[13];
    const float* gW2 = (const float*)d_in[14];
    const float* gb2 = (const float*)d_in[15];

    const int N = in_sizes[0] / NODE_F;
    const int E = in_sizes[2] / EDGE_F;
    float* out = (float*)d_out;

    cudaMemcpyToSymbolAsync(c_eW1, eW1, 912 * sizeof(float), 0, cudaMemcpyDeviceToDevice, 0);
    cudaMemcpyToSymbolAsync(c_eW2, eW2,  96 * sizeof(float), 0, cudaMemcpyDeviceToDevice, 0);
    cudaMemcpyToSymbolAsync(c_eb2, eb2,   6 * sizeof(float), 0, cudaMemcpyDeviceToDevice, 0);
    cudaMemcpyToSymbolAsync(c_nW1, nW1, 528 * sizeof(float), 0, cudaMemcpyDeviceToDevice, 0);
    cudaMemcpyToSymbolAsync(c_nW2, nW2, 384 * sizeof(float), 0, cudaMemcpyDeviceToDevice, 0);
    cudaMemcpyToSymbolAsync(c_nb2, nb2,  24 * sizeof(float), 0, cudaMemcpyDeviceToDevice, 0);

    float *xA, *xB, *pEb, *pNb;
    float2 *ea, *eaP;
    cudaGetSymbolAddress((void**)&xA,  d_xA);
    cudaGetSymbolAddress((void**)&xB,  d_xB);
    cudaGetSymbolAddress((void**)&ea,  d_ea);
    cudaGetSymbolAddress((void**)&eaP, d_eaP);
    cudaGetSymbolAddress((void**)&pEb, d_ebias);
    cudaGetSymbolAddress((void**)&pNb, d_nbias);

    const float invE = 1.0f / (float)E;
    const float invN = 1.0f / (float)N;
    const int GW1S = 11 * HID;

    const int eg = (E + 255) / 256;

    pre_kernel<<<(N + 255) / 256, 256>>>(x0, g0, eb1, nb1, pEb, pNb, N);
    hist_kernel<<<eg, 256>>>(ei, E);
    scan_kernel<<<1, SCAN_T>>>(N);
    perm_kernel<<<eg, 256>>>(ei, ea0, E);

    const int EPB = 32 * ESTEPS;                 // 256 edges / 128-thread block
    const int eblocks = (E + EPB - 1) / EPB;
    const int nblocks = (N + 255) / 256;

    // ---- layer 0 ----
    edge_kernel<0, true><<<eblocks, 128>>>(eaP, pEb + 0 * HID, ea, E);
    node_kernel<0, true><<<nblocks, 256>>>(
        x0, pNb + 0 * HID, xA,
        gW1 + 0 * GW1S, gb1 + 0 * HID, gW2 + 0 * HID, gb2 + 0,
        eb1 + 1 * HID, nb1 + 1 * HID,
        pEb + 1 * HID, pNb + 1 * HID, invE, invN, N);

    // ---- layer 1 ----
    edge_kernel<1, true><<<eblocks, 128>>>(ea, pEb + 1 * HID, ea, E);
    node_kernel<1, true><<<nblocks, 256>>>(
        xA, pNb + 1 * HID, xB,
        gW1 + 1 * GW1S, gb1 + 1 * HID, gW2 + 1 * HID, gb2 + 1,
        eb1 + 2 * HID, nb1 + 2 * HID,
        pEb + 0 * HID, pNb + 0 * HID, invE, invN, N);

    // ---- layer 2 (no ea_out, no global block needed) ----
    edge_kernel<2, false><<<eblocks, 128>>>(ea, pEb + 0 * HID, ea, E);
    node_kernel<2, false><<<nblocks, 256>>>(
        xB, pNb + 0 * HID, out,
        nullptr, nullptr, nullptr, nullptr,
        nullptr, nullptr, nullptr, nullptr, invE, invN, N);
}

// round 15
// speedup vs baseline: 2.0944x; 2.0944x over previous
#include <cuda_runtime.h>

#define NODE_F 8
#define EDGE_F 2
#define HID 16
#define NMAX 100000
#define EMAX 1600000
#define ESTEPS 8   // edges per block = 32 * ESTEPS = 256

// ---- constant-memory weights (filled by async D2D memcpy each call) ----
__constant__ float c_eW1[3 * 19 * HID];  // 912
__constant__ float c_eW2[3 * HID * 2];   // 96
__constant__ float c_eb2[3 * 2];         // 6
__constant__ float c_nW1[3 * 11 * HID];  // 528
__constant__ float c_nW2[3 * HID * 8];   // 384
__constant__ float c_nb2[3 * 8];         // 24

// ---- scratch (__device__ globals per allocation-free rule) ----
__device__ alignas(16) float d_xA[NMAX * NODE_F];
__device__ alignas(16) float d_xB[NMAX * NODE_F];
__device__ alignas(16) float d_ea[EMAX * EDGE_F];
__device__ alignas(16) float d_p[NMAX * HID];     // A_l . x[n]  (64B row, line-aligned)
__device__ alignas(16) float d_q[NMAX * HID];     // B_l . x[n]
__device__ alignas(16) float d_agg[NMAX * EDGE_F];   // zero-init, self-cleaning
__device__ float d_g;
__device__ float d_eacc[EDGE_F];   // zero-init, self-cleaning (fed by node kernel)
__device__ float d_nacc[NODE_F];   // zero-init, self-cleaning
__device__ float d_ebias[2][HID];  // b1_e + g*W1_e[g-row], double buffered
__device__ float d_nbias[2][HID];
__device__ unsigned d_count;       // zero-init, self-cleaning

// ---------------------------------------------------------------------------
// layer-0 p/q precompute from external x; block 0 also folds layer-0 biases.
__global__ __launch_bounds__(256)
void pre_kernel(const float* __restrict__ x,
                const float* __restrict__ g_in,
                const float* __restrict__ eb1, const float* __restrict__ nb1,
                float* __restrict__ ebias0, float* __restrict__ nbias0, int N)
{
    if (blockIdx.x == 0 && threadIdx.x < 32) {
        int t = threadIdx.x;
        float g = g_in[0];
        if (t < HID) {
            ebias0[t] = eb1[t] + g * c_eW1[t];          // edge W1 g-row (layer 0)
            nbias0[t] = nb1[t] + g * c_nW1[t];          // node W1 g-row (layer 0)
        }
        if (t == 0) d_g = g;
    }
    int n = blockIdx.x * blockDim.x + threadIdx.x;
    if (n >= N) return;
    float xv[NODE_F];
    *reinterpret_cast<float4*>(xv)     = *reinterpret_cast<const float4*>(x + (size_t)n * NODE_F);
    *reinterpret_cast<float4*>(xv + 4) = *reinterpret_cast<const float4*>(x + (size_t)n * NODE_F + 4);
    float pv[HID], qv[HID];
    #pragma unroll
    for (int j = 0; j < HID; j++) { pv[j] = 0.f; qv[j] = 0.f; }
    #pragma unroll
    for (int k = 0; k < NODE_F; k++) {
        float v = xv[k];
        #pragma unroll
        for (int j = 0; j < HID; j++) {
            pv[j] = fmaf(v, c_eW1[(1 + k) * HID + j], pv[j]);   // x[row] rows 1..8
            qv[j] = fmaf(v, c_eW1[(9 + k) * HID + j], qv[j]);   // x[col] rows 9..16
        }
    }
    float4* pd = reinterpret_cast<float4*>(d_p + (size_t)n * HID);
    float4* qd = reinterpret_cast<float4*>(d_q + (size_t)n * HID);
    #pragma unroll
    for (int v = 0; v < 4; v++) {
        pd[v] = reinterpret_cast<float4*>(pv)[v];
        qd[v] = reinterpret_cast<float4*>(qv)[v];
    }
}

// ---------------------------------------------------------------------------
// Edge block: 4 lanes per edge, register-hoisted weights; sR/sC/sEA staged in
// smem with coalesced streaming loads. TAIL=false (E divisible by 256): all
// bounds checks removed — every block is full.
template<int L, bool WRITE_EA, bool TAIL>
__global__ __launch_bounds__(128, 12)
void edge_kernel(const int* __restrict__ ei, const float* __restrict__ ea,
                 const float* __restrict__ ebias,
                 float* __restrict__ ea_out, int E)
{
    __shared__ int    sR[32 * ESTEPS], sC[32 * ESTEPS];
    __shared__ float2 sEA[32 * ESTEPS];
    const int tx    = threadIdx.x;
    const int sub   = tx & 3;         // lane within edge-group
    const int group = tx >> 2;        // 0..31 within block
    const int j0    = sub * 4;        // this lane's 4 hidden units
    const int base  = blockIdx.x * (32 * ESTEPS);

    // stage this block's indices + edge attrs (coalesced single-use streams)
    #pragma unroll
    for (int i = tx; i < 32 * ESTEPS; i += 128) {
        int e  = base + i;
        int ec = TAIL ? ((e < E) ? e : 0) : e;
        sR[i]  = __ldcs(ei + ec);
        sC[i]  = __ldcs(ei + E + ec);
        sEA[i] = __ldcs(reinterpret_cast<const float2*>(ea + (size_t)ec * EDGE_F));
    }

    // one-time per-thread weight hoist (overlaps the staging LDGs)
    float c0[4], c1[4], w20[4], w21[4], ebv[4];
    #pragma unroll
    for (int k = 0; k < 4; k++) {
        c0[k]  = c_eW1[L * 304 + 17 * HID + j0 + k];
        c1[k]  = c_eW1[L * 304 + 18 * HID + j0 + k];
        w20[k] = c_eW2[L * 32 + 2 * (j0 + k)];
        w21[k] = c_eW2[L * 32 + 2 * (j0 + k) + 1];
        ebv[k] = ebias[j0 + k];
    }
    const float B20 = c_eb2[L * 2 + 0];
    const float B21 = c_eb2[L * 2 + 1];
    __syncthreads();

    #pragma unroll
    for (int s = 0; s < ESTEPS; s++) {
        const int le = group + s * 32;
        const int e  = base + le;
        if (!TAIL || e < E) {
            int r = sR[le];           // LDS broadcast across the 4 sub-lanes
            int c = sC[le];
            float4 pv = *reinterpret_cast<const float4*>(d_p + (size_t)r * HID + j0);
            float4 qv = *reinterpret_cast<const float4*>(d_q + (size_t)c * HID + j0);
            float2 eav = sEA[le];

            float o0 = 0.f, o1 = 0.f;
            float hp[4] = {pv.x, pv.y, pv.z, pv.w};
            float hq[4] = {qv.x, qv.y, qv.z, qv.w};
            #pragma unroll
            for (int k = 0; k < 4; k++) {
                float h = ebv[k] + hp[k] + hq[k];
                h = fmaf(eav.x, c0[k], h);
                h = fmaf(eav.y, c1[k], h);
                h = fmaxf(h, 0.f);
                o0 = fmaf(h, w20[k], o0);
                o1 = fmaf(h, w21[k], o1);
            }
            // reduce across the 4 sub-lanes
            o0 += __shfl_xor_sync(0xffffffffu, o0, 1);
            o1 += __shfl_xor_sync(0xffffffffu, o1, 1);
            o0 += __shfl_xor_sync(0xffffffffu, o0, 2);
            o1 += __shfl_xor_sync(0xffffffffu, o1, 2);

            if (sub == 0) {
                o0 += B20; o1 += B21;
                if (WRITE_EA)
                    *reinterpret_cast<float2*>(ea_out + (size_t)e * EDGE_F) = make_float2(o0, o1);
                float* dst = &d_agg[(size_t)r * EDGE_F];
                asm volatile("red.global.add.v2.f32 [%0], {%1, %2};"
                             :: "l"(dst), "f"(o0), "f"(o1) : "memory");
            }
        }
    }
}

// ---------------------------------------------------------------------------
// Node block: weights from __constant__ with compile-time layer L.
// FUSE: next-layer p/q, node-sum + edge-sum (from agg) reduction, last block
// runs the global MLP + folds next-layer biases.
template<int L, bool FUSE>
__global__ __launch_bounds__(256)
void node_kernel(const float* __restrict__ x,
                 const float* __restrict__ nbias,
                 float* __restrict__ x_out,
                 const float* __restrict__ gW1, const float* __restrict__ gb1,
                 const float* __restrict__ gW2, const float* __restrict__ gb2,
                 const float* __restrict__ eb1n, const float* __restrict__ nb1n,
                 float* __restrict__ ebias_out, float* __restrict__ nbias_out,
                 float invE, float invN, int N)
{
    __shared__ float sNb[HID];
    __shared__ float sred[NODE_F + 2][8];
    __shared__ bool  isLast;
    int tx = threadIdx.x;
    if (tx < HID) sNb[tx] = nbias[tx];
    __syncthreads();

    int n = blockIdx.x * blockDim.x + tx;
    float out[NODE_F];
    #pragma unroll
    for (int k = 0; k < NODE_F; k++) out[k] = 0.f;
    float2 av = make_float2(0.f, 0.f);

    if (n < N) {
        float xv[NODE_F];
        *reinterpret_cast<float4*>(xv)     = *reinterpret_cast<const float4*>(x + (size_t)n * NODE_F);
        *reinterpret_cast<float4*>(xv + 4) = *reinterpret_cast<const float4*>(x + (size_t)n * NODE_F + 4);
        av = *reinterpret_cast<float2*>(&d_agg[(size_t)n * EDGE_F]);
        *reinterpret_cast<float2*>(&d_agg[(size_t)n * EDGE_F]) = make_float2(0.f, 0.f); // self-clean

        float h[HID];
        #pragma unroll
        for (int j = 0; j < HID; j++) h[j] = sNb[j];
        #pragma unroll
        for (int i = 0; i < NODE_F; i++) {
            float v = xv[i];
            #pragma unroll
            for (int j = 0; j < HID; j++)
                h[j] = fmaf(v, c_nW1[L * 176 + (1 + i) * HID + j], h[j]);  // x rows 1..8
        }
        #pragma unroll
        for (int j = 0; j < HID; j++) {
            h[j] = fmaf(av.x, c_nW1[L * 176 + 9 * HID + j], h[j]);
            h[j] = fmaf(av.y, c_nW1[L * 176 + 10 * HID + j], h[j]);
        }
        #pragma unroll
        for (int k = 0; k < NODE_F; k++) out[k] = c_nb2[L * 8 + k];
        #pragma unroll
        for (int j = 0; j < HID; j++) {
            float hv = fmaxf(h[j], 0.f);
            #pragma unroll
            for (int k = 0; k < NODE_F; k++)
                out[k] = fmaf(hv, c_nW2[L * 128 + j * 8 + k], out[k]);
        }
        *reinterpret_cast<float4*>(x_out + (size_t)n * NODE_F)     = *reinterpret_cast<float4*>(out);
        *reinterpret_cast<float4*>(x_out + (size_t)n * NODE_F + 4) = *reinterpret_cast<float4*>(out + 4);

        if (FUSE) {   // next-layer p/q from the fresh embedding (const weights, layer L+1)
            constexpr int EOFF = (L + 1) * 304;
            float pv[HID], qv[HID];
            #pragma unroll
            for (int j = 0; j < HID; j++) { pv[j] = 0.f; qv[j] = 0.f; }
            #pragma unroll
            for (int k = 0; k < NODE_F; k++) {
                float v = out[k];
                #pragma unroll
                for (int j = 0; j < HID; j++) {
                    pv[j] = fmaf(v, c_eW1[EOFF + (1 + k) * HID + j], pv[j]);
                    qv[j] = fmaf(v, c_eW1[EOFF + (9 + k) * HID + j], qv[j]);
                }
            }
            float4* pd = reinterpret_cast<float4*>(d_p + (size_t)n * HID);
            float4* qd = reinterpret_cast<float4*>(d_q + (size_t)n * HID);
            #pragma unroll
            for (int v = 0; v < 4; v++) {
                pd[v] = reinterpret_cast<float4*>(pv)[v];
                qd[v] = reinterpret_cast<float4*>(qv)[v];
            }
        }
    }

    if (FUSE) {
        // block reduction: 8 node-emb sums + 2 agg sums (= edge-emb sums)
        int warp = tx >> 5, lane = tx & 31;
        #pragma unroll
        for (int k = 0; k < NODE_F + 2; k++) {
            float s = (k < NODE_F) ? out[k] : ((k == NODE_F) ? av.x : av.y);
            #pragma unroll
            for (int off = 16; off; off >>= 1)
                s += __shfl_down_sync(0xffffffffu, s, off);
            if (lane == 0) sred[k][warp] = s;
        }
        __syncthreads();
        if (tx < NODE_F + 2) {
            float t = 0.f;
            #pragma unroll
            for (int w = 0; w < 8; w++) t += sred[tx][w];
            if (tx < NODE_F) atomicAdd(&d_nacc[tx], t);
            else             atomicAdd(&d_eacc[tx - NODE_F], t);
            __threadfence();
        }
        __syncthreads();
        if (tx == 0) {
            unsigned t = atomicAdd(&d_count, 1u);
            isLast = (t == gridDim.x - 1);
        }
        __syncthreads();

        if (isLast) {
            __threadfence();
            if (tx < 32) {
                float gv = d_g;
                float h = 0.f;
                if (tx < HID) {
                    h = gb1[tx];
                    #pragma unroll
                    for (int i = 0; i < NODE_F; i++)
                        h = fmaf(d_nacc[i] * invN, gW1[i * HID + tx], h);
                    h = fmaf(d_eacc[0] * invE, gW1[8 * HID + tx], h);
                    h = fmaf(d_eacc[1] * invE, gW1[9 * HID + tx], h);
                    h = fmaf(gv, gW1[10 * HID + tx], h);
                    h = fmaxf(h, 0.f) * gW2[tx];
                }
                #pragma unroll
                for (int off = 16; off; off >>= 1)
                    h += __shfl_down_sync(0xffffffffu, h, off);
                float gn = __shfl_sync(0xffffffffu, h, 0) + gb2[0];
                if (tx == 0) d_g = gn;
                if (tx < HID) {
                    ebias_out[tx] = eb1n[tx] + gn * c_eW1[(L + 1) * 304 + tx];
                    nbias_out[tx] = nb1n[tx] + gn * c_nW1[(L + 1) * 176 + tx];
                }
                if (tx < NODE_F) d_nacc[tx] = 0.f;   // self-clean
                if (tx < EDGE_F) d_eacc[tx] = 0.f;
                if (tx == 0)     d_count = 0u;
            }
        }
    }
}

// ---------------------------------------------------------------------------
extern "C" void kernel_launch(void* const* d_in, const int* in_sizes, int n_in,
                              void* d_out, int out_size)
{
    const float* x0  = (const float*)d_in[0];
    const int*   ei  = (const int*)  d_in[1];
    const float* ea0 = (const float*)d_in[2];
    const float* g0  = (const float*)d_in[3];
    const float* eW1 = (const float*)d_in[4];
    const float* eb1 = (const float*)d_in[5];
    const float* eW2 = (const float*)d_in[6];
    const float* eb2 = (const float*)d_in[7];
    const float* nW1 = (const float*)d_in[8];
    const float* nb1 = (const float*)d_in[9];
    const float* nW2 = (const float*)d_in[10];
    const float* nb2 = (const float*)d_in[11];
    const float* gW1 = (const float*)d_in[12];
    const float* gb1 = (const float*)d_in[13];
    const float* gW2 = (const float*)d_in[14];
    const float* gb2 = (const float*)d_in[15];

    const int N = in_sizes[0] / NODE_F;
    const int E = in_sizes[2] / EDGE_F;
    float* out = (float*)d_out;

    // stage weights into constant memory (D2D, graph-capturable)
    cudaMemcpyToSymbolAsync(c_eW1, eW1, 912 * sizeof(float), 0, cudaMemcpyDeviceToDevice, 0);
    cudaMemcpyToSymbolAsync(c_eW2, eW2,  96 * sizeof(float), 0, cudaMemcpyDeviceToDevice, 0);
    cudaMemcpyToSymbolAsync(c_eb2, eb2,   6 * sizeof(float), 0, cudaMemcpyDeviceToDevice, 0);
    cudaMemcpyToSymbolAsync(c_nW1, nW1, 528 * sizeof(float), 0, cudaMemcpyDeviceToDevice, 0);
    cudaMemcpyToSymbolAsync(c_nW2, nW2, 384 * sizeof(float), 0, cudaMemcpyDeviceToDevice, 0);
    cudaMemcpyToSymbolAsync(c_nb2, nb2,  24 * sizeof(float), 0, cudaMemcpyDeviceToDevice, 0);

    float *xA, *xB, *ea, *pEb, *pNb;
    cudaGetSymbolAddress((void**)&xA,  d_xA);
    cudaGetSymbolAddress((void**)&xB,  d_xB);
    cudaGetSymbolAddress((void**)&ea,  d_ea);
    cudaGetSymbolAddress((void**)&pEb, d_ebias);
    cudaGetSymbolAddress((void**)&pNb, d_nbias);

    const float invE = 1.0f / (float)E;
    const float invN = 1.0f / (float)N;
    const int GW1S = 11 * HID;

    pre_kernel<<<(N + 255) / 256, 256>>>(x0, g0, eb1, nb1, pEb, pNb, N);

    const int EPB = 32 * ESTEPS;                 // 256 edges / 128-thread block
    const int eblocks = (E + EPB - 1) / EPB;
    const int nblocks = (N + 255) / 256;
    const bool tail = (E % EPB) != 0;

    // ---- layer 0 ----
    if (tail) edge_kernel<0, true, true ><<<eblocks, 128>>>(ei, ea0, pEb + 0 * HID, ea, E);
    else      edge_kernel<0, true, false><<<eblocks, 128>>>(ei, ea0, pEb + 0 * HID, ea, E);
    node_kernel<0, true><<<nblocks, 256>>>(
        x0, pNb + 0 * HID, xA,
        gW1 + 0 * GW1S, gb1 + 0 * HID, gW2 + 0 * HID, gb2 + 0,
        eb1 + 1 * HID, nb1 + 1 * HID,
        pEb + 1 * HID, pNb + 1 * HID, invE, invN, N);

    // ---- layer 1 ----
    if (tail) edge_kernel<1, true, true ><<<eblocks, 128>>>(ei, ea, pEb + 1 * HID, ea, E);
    else      edge_kernel<1, true, false><<<eblocks, 128>>>(ei, ea, pEb + 1 * HID, ea, E);
    node_kernel<1, true><<<nblocks, 256>>>(
        xA, pNb + 1 * HID, xB,
        gW1 + 1 * GW1S, gb1 + 1 * HID, gW2 + 1 * HID, gb2 + 1,
        eb1 + 2 * HID, nb1 + 2 * HID,
        pEb + 0 * HID, pNb + 0 * HID, invE, invN, N);

    // ---- layer 2 (no ea_out, no global block needed) ----
    if (tail) edge_kernel<2, false, true ><<<eblocks, 128>>>(ei, ea, pEb + 0 * HID, ea, E);
    else      edge_kernel<2, false, false><<<eblocks, 128>>>(ei, ea, pEb + 0 * HID, ea, E);
    node_kernel<2, false><<<nblocks, 256>>>(
        xB, pNb + 0 * HID, out,
        nullptr, nullptr, nullptr, nullptr,
        nullptr, nullptr, nullptr, nullptr, invE, invN, N);
}